// round 1
// baseline (speedup 1.0000x reference)
#include <cuda_runtime.h>

// RecursiveEncoder fused kernel — fp32 SIMT baseline.
//
// Shapes:
//   box_input [32768,10,10], eps [32768,256]
//   W_box [10,256], b_box[256]
//   W1 [320,256] (rows 0..255 multiply leaf, rows 256..319 are one-hot addends)
//   W2/Ws1/Wmu/Wvar [256,256], biases [256]
//   sem_ids [32768,10] int32, n_children [32768] int32
//   out [32768, 512] fp32  (concat of sample, kld)

#define B_N   32768
#define PT    64          // parents per block
#define NT    512         // threads per block
#define MAXC  10

struct Smem {
    float As[PT * 256];     // leaf tile / X / E buffer
    float Bf[PT * 256];     // P buffer
    float Ws[32 * 256];     // weight k-chunk
    float box[PT * 100];    // [64][10][10]
    float wbox[10 * 256];
    float bbox[256];
    int   sem[PT * 10];
    int   nc[PT];
};

// acc[4][8] += As[64x256] @ Wg[256x256] for this thread's 4 rows x 8 strided cols.
// Rows: rg*4 + i. Cols: cg + j*32.
__device__ __forceinline__ void gemm_64x256(
    const float* __restrict__ As,   // smem [64][256]
    const float* __restrict__ Wg,   // global, row-major [>=256][256]
    float* __restrict__ Ws,         // smem [32][256]
    int t, int rg, int cg,
    float acc[4][8])
{
    #pragma unroll 1
    for (int kc = 0; kc < 256; kc += 32) {
        __syncthreads();   // previous users of Ws are done
        #pragma unroll
        for (int u = 0; u < 16; u++) {
            int i = t + u * NT;                       // 32*256 / 512 = 16 each
            Ws[i] = Wg[((kc + (i >> 8)) << 8) + (i & 255)];
        }
        __syncthreads();
        #pragma unroll 2
        for (int k4 = 0; k4 < 8; k4++) {
            float4 a0 = *(const float4*)&As[((rg * 4 + 0) << 8) + kc + k4 * 4];
            float4 a1 = *(const float4*)&As[((rg * 4 + 1) << 8) + kc + k4 * 4];
            float4 a2 = *(const float4*)&As[((rg * 4 + 2) << 8) + kc + k4 * 4];
            float4 a3 = *(const float4*)&As[((rg * 4 + 3) << 8) + kc + k4 * 4];
            const float* av0 = (const float*)&a0;
            const float* av1 = (const float*)&a1;
            const float* av2 = (const float*)&a2;
            const float* av3 = (const float*)&a3;
            #pragma unroll
            for (int kk = 0; kk < 4; kk++) {
                #pragma unroll
                for (int j = 0; j < 8; j++) {
                    float w = Ws[((k4 * 4 + kk) << 8) + cg + j * 32];
                    acc[0][j] += av0[kk] * w;
                    acc[1][j] += av1[kk] * w;
                    acc[2][j] += av2[kk] * w;
                    acc[3][j] += av3[kk] * w;
                }
            }
        }
    }
}

__global__ void __launch_bounds__(NT, 1)
recenc_fused_kernel(const float* __restrict__ box_input,
                    const float* __restrict__ eps,
                    const float* __restrict__ W_box,
                    const float* __restrict__ b_box,
                    const float* __restrict__ W1,
                    const float* __restrict__ b1,
                    const float* __restrict__ W2,
                    const float* __restrict__ b2,
                    const float* __restrict__ Ws1,
                    const float* __restrict__ bs1,
                    const float* __restrict__ Wmu,
                    const float* __restrict__ bmu,
                    const float* __restrict__ Wvar,
                    const float* __restrict__ bvar,
                    const int*   __restrict__ sem_ids,
                    const int*   __restrict__ n_children,
                    float*       __restrict__ out)
{
    extern __shared__ float smem_raw[];
    Smem* S = (Smem*)smem_raw;
    const int t  = threadIdx.x;
    const int b0 = blockIdx.x * PT;
    const int rg = t >> 5;     // 0..15  -> rows rg*4 .. rg*4+3
    const int cg = t & 31;     // 0..31  -> cols cg + j*32

    // ---- stage per-tile inputs ----
    for (int i = t; i < PT * 100; i += NT) S->box[i] = box_input[b0 * 100 + i];
    for (int i = t; i < 10 * 256; i += NT) S->wbox[i] = W_box[i];
    if (t < 256) S->bbox[t] = b_box[t];
    for (int i = t; i < PT * 10; i += NT) S->sem[i] = sem_ids[b0 * 10 + i];
    if (t < PT) S->nc[t] = n_children[b0 + t];
    __syncthreads();

    float bb1[8];
    #pragma unroll
    for (int j = 0; j < 8; j++) bb1[j] = b1[cg + j * 32];

    float macc[4][8];
    #pragma unroll
    for (int i = 0; i < 4; i++)
        #pragma unroll
        for (int j = 0; j < 8; j++) macc[i][j] = 0.0f;

    // ---- children loop: leaf -> W1 GEMM -> masked max ----
    for (int m = 0; m < MAXC; m++) {
        __syncthreads();   // prior GEMM done reading As
        // leaf = relu(box @ W_box + b_box) for child m, into As [64][256]
        #pragma unroll 2
        for (int u = 0; u < (PT * 256) / NT; u++) {
            int i = t + u * NT;
            int r = i >> 8, f = i & 255;
            float s = S->bbox[f];
            const float* bx = &S->box[r * 100 + m * 10];
            #pragma unroll
            for (int q = 0; q < 10; q++) s += bx[q] * S->wbox[q * 256 + f];
            S->As[i] = fmaxf(s, 0.0f);
        }
        float facc[4][8];
        #pragma unroll
        for (int i = 0; i < 4; i++)
            #pragma unroll
            for (int j = 0; j < 8; j++) facc[i][j] = 0.0f;
        gemm_64x256(S->As, W1, S->Ws, t, rg, cg, facc);

        // epilogue: + one-hot row of W1 + b1, relu, masked running max
        #pragma unroll
        for (int i = 0; i < 4; i++) {
            int rr = rg * 4 + i;
            if (m < S->nc[rr]) {
                const float* wrow = W1 + ((256 + S->sem[rr * 10 + m]) << 8) + cg;
                #pragma unroll
                for (int j = 0; j < 8; j++) {
                    float v = facc[i][j] + wrow[j * 32] + bb1[j];
                    macc[i][j] = fmaxf(macc[i][j], fmaxf(v, 0.0f));
                }
            }
        }
    }

    // ---- x = macc -> As (X buffer) ----
    __syncthreads();
    #pragma unroll
    for (int i = 0; i < 4; i++)
        #pragma unroll
        for (int j = 0; j < 8; j++)
            S->As[(rg * 4 + i) * 256 + cg + j * 32] = macc[i][j];

    float acc[4][8];

    // ---- parent_feat = relu(X @ W2 + b2) -> Bf ----
    #pragma unroll
    for (int i = 0; i < 4; i++)
        #pragma unroll
        for (int j = 0; j < 8; j++) acc[i][j] = 0.0f;
    gemm_64x256(S->As, W2, S->Ws, t, rg, cg, acc);
    {
        float bb[8];
        #pragma unroll
        for (int j = 0; j < 8; j++) bb[j] = b2[cg + j * 32];
        #pragma unroll
        for (int i = 0; i < 4; i++)
            #pragma unroll
            for (int j = 0; j < 8; j++)
                S->Bf[(rg * 4 + i) * 256 + cg + j * 32] = fmaxf(acc[i][j] + bb[j], 0.0f);
    }

    // ---- enc = relu(P @ Ws1 + bs1) -> As ----
    #pragma unroll
    for (int i = 0; i < 4; i++)
        #pragma unroll
        for (int j = 0; j < 8; j++) acc[i][j] = 0.0f;
    gemm_64x256(S->Bf, Ws1, S->Ws, t, rg, cg, acc);
    {
        float bb[8];
        #pragma unroll
        for (int j = 0; j < 8; j++) bb[j] = bs1[cg + j * 32];
        __syncthreads();   // all GEMM readers of As (from W2 stage) long done; keep ordering explicit
        #pragma unroll
        for (int i = 0; i < 4; i++)
            #pragma unroll
            for (int j = 0; j < 8; j++)
                S->As[(rg * 4 + i) * 256 + cg + j * 32] = fmaxf(acc[i][j] + bb[j], 0.0f);
    }

    // ---- mu = enc @ Wmu + bmu (kept in regs) ----
    #pragma unroll
    for (int i = 0; i < 4; i++)
        #pragma unroll
        for (int j = 0; j < 8; j++) acc[i][j] = 0.0f;
    gemm_64x256(S->As, Wmu, S->Ws, t, rg, cg, acc);
    float mu[4][8];
    {
        float bb[8];
        #pragma unroll
        for (int j = 0; j < 8; j++) bb[j] = bmu[cg + j * 32];
        #pragma unroll
        for (int i = 0; i < 4; i++)
            #pragma unroll
            for (int j = 0; j < 8; j++) mu[i][j] = acc[i][j] + bb[j];
    }

    // ---- logvar = enc @ Wvar + bvar, then sampler epilogue ----
    #pragma unroll
    for (int i = 0; i < 4; i++)
        #pragma unroll
        for (int j = 0; j < 8; j++) acc[i][j] = 0.0f;
    gemm_64x256(S->As, Wvar, S->Ws, t, rg, cg, acc);
    {
        float bb[8];
        #pragma unroll
        for (int j = 0; j < 8; j++) bb[j] = bvar[cg + j * 32];
        #pragma unroll
        for (int i = 0; i < 4; i++) {
            int b = b0 + rg * 4 + i;
            #pragma unroll
            for (int j = 0; j < 8; j++) {
                int c = cg + j * 32;
                float lv  = acc[i][j] + bb[j];
                float muv = mu[i][j];
                float e   = eps[b * 256 + c];
                float sd  = expf(0.5f * lv);
                float ex  = sd * sd;                 // exp(lv)
                out[b * 512 + c]       = e * sd + muv;
                out[b * 512 + 256 + c] = 1.0f + lv - muv * muv - ex;
            }
        }
    }
}

extern "C" void kernel_launch(void* const* d_in, const int* in_sizes, int n_in,
                              void* d_out, int out_size)
{
    const float* box   = (const float*)d_in[0];
    const float* eps   = (const float*)d_in[1];
    const float* W_box = (const float*)d_in[2];
    const float* b_box = (const float*)d_in[3];
    const float* W1    = (const float*)d_in[4];
    const float* b1    = (const float*)d_in[5];
    const float* W2    = (const float*)d_in[6];
    const float* b2    = (const float*)d_in[7];
    const float* Ws1   = (const float*)d_in[8];
    const float* bs1   = (const float*)d_in[9];
    const float* Wmu   = (const float*)d_in[10];
    const float* bmu   = (const float*)d_in[11];
    const float* Wvar  = (const float*)d_in[12];
    const float* bvar  = (const float*)d_in[13];
    const int*   sem   = (const int*)d_in[14];
    const int*   nc    = (const int*)d_in[15];
    float* out = (float*)d_out;

    size_t shmem = sizeof(Smem);
    cudaFuncSetAttribute(recenc_fused_kernel,
                         cudaFuncAttributeMaxDynamicSharedMemorySize, (int)shmem);
    recenc_fused_kernel<<<B_N / PT, NT, shmem>>>(
        box, eps, W_box, b_box, W1, b1, W2, b2,
        Ws1, bs1, Wmu, bmu, Wvar, bvar, sem, nc, out);
}

// round 2
// speedup vs baseline: 1.1842x; 1.1842x over previous
#include <cuda_runtime.h>

// RecursiveEncoder fused kernel — fp32 SIMT with packed f32x2 FFMA2 inner loop.

#define B_N   32768
#define PT    64          // parents per block
#define NT    512         // threads per block
#define MAXC  10

struct Smem {
    float As[PT * 256];     // leaf tile / X / E buffer
    float Bf[PT * 256];     // P buffer
    float Ws[32 * 256];     // weight k-chunk
    float box[PT * 100];    // [64][10][10]
    float wbox[10 * 256];
    float bbox[256];
    int   sem[PT * 10];
    int   nc[PT];
};

typedef unsigned long long u64;

__device__ __forceinline__ void ffma2(u64& d, u64 a, u64 b) {
    asm("fma.rn.f32x2 %0, %1, %2, %0;" : "+l"(d) : "l"(a), "l"(b));
}
__device__ __forceinline__ u64 splat2(float x) {
    u64 r;
    asm("mov.b64 %0, {%1, %1};" : "=l"(r) : "f"(x));
    return r;
}
__device__ __forceinline__ float2 unpack2(u64 v) {
    float2 r;
    asm("mov.b64 {%0, %1}, %2;" : "=f"(r.x), "=f"(r.y) : "l"(v));
    return r;
}

// acc[4][4] (f32x2 pairs) += As[64x256] @ Wg[256x256].
// Rows: rg*4 + i. Col pairs: {2*cg + jp*64, 2*cg + jp*64 + 1}, jp=0..3.
__device__ __forceinline__ void gemm_64x256_p2(
    const float* __restrict__ As,
    const float* __restrict__ Wg,
    float* __restrict__ Ws,
    int t, int rg, int cg,
    u64 acc[4][4])
{
    const int c0 = 2 * cg;
    #pragma unroll 1
    for (int kc = 0; kc < 256; kc += 32) {
        __syncthreads();   // previous users of Ws are done
        #pragma unroll
        for (int u = 0; u < 16; u++) {
            int i = t + u * NT;                       // 32*256 / 512 = 16 each
            Ws[i] = Wg[((kc + (i >> 8)) << 8) + (i & 255)];
        }
        __syncthreads();
        #pragma unroll 2
        for (int k4 = 0; k4 < 8; k4++) {
            float4 a0 = *(const float4*)&As[((rg * 4 + 0) << 8) + kc + k4 * 4];
            float4 a1 = *(const float4*)&As[((rg * 4 + 1) << 8) + kc + k4 * 4];
            float4 a2 = *(const float4*)&As[((rg * 4 + 2) << 8) + kc + k4 * 4];
            float4 a3 = *(const float4*)&As[((rg * 4 + 3) << 8) + kc + k4 * 4];
            const float* av0 = (const float*)&a0;
            const float* av1 = (const float*)&a1;
            const float* av2 = (const float*)&a2;
            const float* av3 = (const float*)&a3;
            #pragma unroll
            for (int kk = 0; kk < 4; kk++) {
                u64 s0 = splat2(av0[kk]);
                u64 s1 = splat2(av1[kk]);
                u64 s2 = splat2(av2[kk]);
                u64 s3 = splat2(av3[kk]);
                const float* wrow = &Ws[((k4 * 4 + kk) << 8) + c0];
                #pragma unroll
                for (int jp = 0; jp < 4; jp++) {
                    u64 w2 = *(const u64*)&wrow[jp * 64];   // LDS.64, conflict-free
                    ffma2(acc[0][jp], s0, w2);
                    ffma2(acc[1][jp], s1, w2);
                    ffma2(acc[2][jp], s2, w2);
                    ffma2(acc[3][jp], s3, w2);
                }
            }
        }
    }
}

__device__ __forceinline__ void zero_acc(u64 acc[4][4]) {
    #pragma unroll
    for (int i = 0; i < 4; i++)
        #pragma unroll
        for (int jp = 0; jp < 4; jp++) acc[i][jp] = 0ull;
}

__global__ void __launch_bounds__(NT, 1)
recenc_fused_kernel(const float* __restrict__ box_input,
                    const float* __restrict__ eps,
                    const float* __restrict__ W_box,
                    const float* __restrict__ b_box,
                    const float* __restrict__ W1,
                    const float* __restrict__ b1,
                    const float* __restrict__ W2,
                    const float* __restrict__ b2,
                    const float* __restrict__ Ws1,
                    const float* __restrict__ bs1,
                    const float* __restrict__ Wmu,
                    const float* __restrict__ bmu,
                    const float* __restrict__ Wvar,
                    const float* __restrict__ bvar,
                    const int*   __restrict__ sem_ids,
                    const int*   __restrict__ n_children,
                    float*       __restrict__ out)
{
    extern __shared__ float smem_raw[];
    Smem* S = (Smem*)smem_raw;
    const int t  = threadIdx.x;
    const int b0 = blockIdx.x * PT;
    const int rg = t >> 5;     // 0..15  -> rows rg*4 .. rg*4+3
    const int cg = t & 31;
    const int c0 = 2 * cg;     // col pairs c0 + jp*64 + {0,1}

    // ---- stage per-tile inputs ----
    for (int i = t; i < PT * 100; i += NT) S->box[i] = box_input[b0 * 100 + i];
    for (int i = t; i < 10 * 256; i += NT) S->wbox[i] = W_box[i];
    if (t < 256) S->bbox[t] = b_box[t];
    for (int i = t; i < PT * 10; i += NT) S->sem[i] = sem_ids[b0 * 10 + i];
    if (t < PT) S->nc[t] = n_children[b0 + t];
    __syncthreads();

    float2 bb1[4];
    #pragma unroll
    for (int jp = 0; jp < 4; jp++) bb1[jp] = *(const float2*)&b1[c0 + jp * 64];

    float2 macc[4][4];
    #pragma unroll
    for (int i = 0; i < 4; i++)
        #pragma unroll
        for (int jp = 0; jp < 4; jp++) macc[i][jp] = make_float2(0.0f, 0.0f);

    // ---- children loop: leaf -> W1 GEMM -> masked max ----
    for (int m = 0; m < MAXC; m++) {
        __syncthreads();   // prior GEMM done reading As
        // leaf = relu(box @ W_box + b_box) for child m, into As [64][256]
        #pragma unroll 2
        for (int u = 0; u < (PT * 256) / NT; u++) {
            int i = t + u * NT;
            int r = i >> 8, f = i & 255;
            float s = S->bbox[f];
            const float* bx = &S->box[r * 100 + m * 10];
            #pragma unroll
            for (int q = 0; q < 10; q++) s += bx[q] * S->wbox[q * 256 + f];
            S->As[i] = fmaxf(s, 0.0f);
        }
        u64 facc[4][4];
        zero_acc(facc);
        gemm_64x256_p2(S->As, W1, S->Ws, t, rg, cg, facc);

        // epilogue: + one-hot row of W1 + b1, relu, masked running max
        #pragma unroll
        for (int i = 0; i < 4; i++) {
            int rr = rg * 4 + i;
            if (m < S->nc[rr]) {
                const float* wrow = W1 + ((256 + S->sem[rr * 10 + m]) << 8) + c0;
                #pragma unroll
                for (int jp = 0; jp < 4; jp++) {
                    float2 v = unpack2(facc[i][jp]);
                    float2 w = *(const float2*)&wrow[jp * 64];
                    float vx = fmaxf(v.x + w.x + bb1[jp].x, 0.0f);
                    float vy = fmaxf(v.y + w.y + bb1[jp].y, 0.0f);
                    macc[i][jp].x = fmaxf(macc[i][jp].x, vx);
                    macc[i][jp].y = fmaxf(macc[i][jp].y, vy);
                }
            }
        }
    }

    // ---- x = macc -> As (X buffer) ----
    __syncthreads();
    #pragma unroll
    for (int i = 0; i < 4; i++)
        #pragma unroll
        for (int jp = 0; jp < 4; jp++)
            *(float2*)&S->As[(rg * 4 + i) * 256 + c0 + jp * 64] = macc[i][jp];

    u64 acc[4][4];

    // ---- parent_feat = relu(X @ W2 + b2) -> Bf ----
    zero_acc(acc);
    gemm_64x256_p2(S->As, W2, S->Ws, t, rg, cg, acc);
    {
        #pragma unroll
        for (int jp = 0; jp < 4; jp++) {
            float2 bb = *(const float2*)&b2[c0 + jp * 64];
            #pragma unroll
            for (int i = 0; i < 4; i++) {
                float2 v = unpack2(acc[i][jp]);
                v.x = fmaxf(v.x + bb.x, 0.0f);
                v.y = fmaxf(v.y + bb.y, 0.0f);
                *(float2*)&S->Bf[(rg * 4 + i) * 256 + c0 + jp * 64] = v;
            }
        }
    }

    // ---- enc = relu(P @ Ws1 + bs1) -> As ----
    zero_acc(acc);
    gemm_64x256_p2(S->Bf, Ws1, S->Ws, t, rg, cg, acc);
    {
        __syncthreads();   // GEMM readers of As done
        #pragma unroll
        for (int jp = 0; jp < 4; jp++) {
            float2 bb = *(const float2*)&bs1[c0 + jp * 64];
            #pragma unroll
            for (int i = 0; i < 4; i++) {
                float2 v = unpack2(acc[i][jp]);
                v.x = fmaxf(v.x + bb.x, 0.0f);
                v.y = fmaxf(v.y + bb.y, 0.0f);
                *(float2*)&S->As[(rg * 4 + i) * 256 + c0 + jp * 64] = v;
            }
        }
    }

    // ---- mu = enc @ Wmu + bmu (kept in regs) ----
    u64 muacc[4][4];
    zero_acc(muacc);
    gemm_64x256_p2(S->As, Wmu, S->Ws, t, rg, cg, muacc);

    // ---- logvar = enc @ Wvar + bvar, then sampler epilogue ----
    zero_acc(acc);
    gemm_64x256_p2(S->As, Wvar, S->Ws, t, rg, cg, acc);
    {
        #pragma unroll
        for (int jp = 0; jp < 4; jp++) {
            float2 bbv = *(const float2*)&bvar[c0 + jp * 64];
            float2 bbm = *(const float2*)&bmu[c0 + jp * 64];
            #pragma unroll
            for (int i = 0; i < 4; i++) {
                int b = b0 + rg * 4 + i;
                int c = c0 + jp * 64;
                float2 lv = unpack2(acc[i][jp]);
                float2 mv = unpack2(muacc[i][jp]);
                lv.x += bbv.x;  lv.y += bbv.y;
                mv.x += bbm.x;  mv.y += bbm.y;
                float2 e = *(const float2*)&eps[b * 256 + c];
                float sdx = expf(0.5f * lv.x);
                float sdy = expf(0.5f * lv.y);
                float2 samp, kld;
                samp.x = e.x * sdx + mv.x;
                samp.y = e.y * sdy + mv.y;
                kld.x = 1.0f + lv.x - mv.x * mv.x - sdx * sdx;
                kld.y = 1.0f + lv.y - mv.y * mv.y - sdy * sdy;
                *(float2*)&out[b * 512 + c]       = samp;
                *(float2*)&out[b * 512 + 256 + c] = kld;
            }
        }
    }
}

extern "C" void kernel_launch(void* const* d_in, const int* in_sizes, int n_in,
                              void* d_out, int out_size)
{
    const float* box   = (const float*)d_in[0];
    const float* eps   = (const float*)d_in[1];
    const float* W_box = (const float*)d_in[2];
    const float* b_box = (const float*)d_in[3];
    const float* W1    = (const float*)d_in[4];
    const float* b1    = (const float*)d_in[5];
    const float* W2    = (const float*)d_in[6];
    const float* b2    = (const float*)d_in[7];
    const float* Ws1   = (const float*)d_in[8];
    const float* bs1   = (const float*)d_in[9];
    const float* Wmu   = (const float*)d_in[10];
    const float* bmu   = (const float*)d_in[11];
    const float* Wvar  = (const float*)d_in[12];
    const float* bvar  = (const float*)d_in[13];
    const int*   sem   = (const int*)d_in[14];
    const int*   nc    = (const int*)d_in[15];
    float* out = (float*)d_out;

    size_t shmem = sizeof(Smem);
    cudaFuncSetAttribute(recenc_fused_kernel,
                         cudaFuncAttributeMaxDynamicSharedMemorySize, (int)shmem);
    recenc_fused_kernel<<<B_N / PT, NT, shmem>>>(
        box, eps, W_box, b_box, W1, b1, W2, b2,
        Ws1, bs1, Wmu, bmu, Wvar, bvar, sem, nc, out);
}

// round 4
// speedup vs baseline: 1.2617x; 1.0655x over previous
#include <cuda_runtime.h>

// RecursiveEncoder fused kernel — fp32, FFMA2, 8x8 register tile, NT=256.

#define B_N   32768
#define PT    64          // parents per block
#define NT    256         // threads per block
#define MAXC  10
#define KC    64          // k-chunk rows staged in smem

struct Smem {
    float As[PT * 256];     // activation buffer (leaf / X / P / E, reused in place)
    float Ws[KC * 256];     // weight k-chunk
    float box[PT * 100];    // [64][10][10]
    float wbox[10 * 256];
    float bbox[256];
    int   sem[PT * 10];
    int   nc[PT];
};

typedef unsigned long long u64;

__device__ __forceinline__ void ffma2(u64& d, u64 a, u64 b) {
    asm("fma.rn.f32x2 %0, %1, %2, %0;" : "+l"(d) : "l"(a), "l"(b));
}
__device__ __forceinline__ u64 splat2(float x) {
    u64 r;
    asm("mov.b64 %0, {%1, %1};" : "=l"(r) : "f"(x));
    return r;
}
__device__ __forceinline__ float2 unpack2(u64 v) {
    float2 r;
    asm("mov.b64 {%0, %1}, %2;" : "=f"(r.x), "=f"(r.y) : "l"(v));
    return r;
}

// acc[8][4] (f32x2 pairs) += As[64x256] @ Wg[256x256].
// Rows: rg*8 + i (rg = warp id -> A loads are warp-broadcast LDS).
// Col pairs: {2*cg + jp*64, 2*cg + jp*64 + 1}, jp=0..3.
__device__ __forceinline__ void gemm_64x256_p2(
    const float* __restrict__ As,
    const float* __restrict__ Wg,
    float* __restrict__ Ws,
    int t, int rg, int cg,
    u64 acc[8][4])
{
    const int c0 = 2 * cg;
    #pragma unroll 1
    for (int kc = 0; kc < 256; kc += KC) {
        __syncthreads();   // previous users of Ws are done
        #pragma unroll
        for (int u = 0; u < (KC * 256) / NT; u++) {
            int i = t + u * NT;
            Ws[i] = Wg[((kc + (i >> 8)) << 8) + (i & 255)];
        }
        __syncthreads();
        #pragma unroll 1
        for (int k4 = 0; k4 < KC / 4; k4++) {
            float4 av[8];
            #pragma unroll
            for (int i = 0; i < 8; i++)
                av[i] = *(const float4*)&As[((rg * 8 + i) << 8) + kc + k4 * 4];
            const float* af = (const float*)av;
            #pragma unroll
            for (int kk = 0; kk < 4; kk++) {
                u64 s[8];
                #pragma unroll
                for (int i = 0; i < 8; i++) s[i] = splat2(af[i * 4 + kk]);
                const float* wrow = &Ws[((k4 * 4 + kk) << 8) + c0];
                #pragma unroll
                for (int jp = 0; jp < 4; jp++) {
                    u64 w2 = *(const u64*)&wrow[jp * 64];   // LDS.64, conflict-free
                    #pragma unroll
                    for (int i = 0; i < 8; i++) ffma2(acc[i][jp], s[i], w2);
                }
            }
        }
    }
}

__device__ __forceinline__ void zero_acc(u64 acc[8][4]) {
    #pragma unroll
    for (int i = 0; i < 8; i++)
        #pragma unroll
        for (int jp = 0; jp < 4; jp++) acc[i][jp] = 0ull;
}

__global__ void __launch_bounds__(NT, 1)
recenc_fused_kernel(const float* __restrict__ box_input,
                    const float* __restrict__ eps,
                    const float* __restrict__ W_box,
                    const float* __restrict__ b_box,
                    const float* __restrict__ W1,
                    const float* __restrict__ b1,
                    const float* __restrict__ W2,
                    const float* __restrict__ b2,
                    const float* __restrict__ Ws1,
                    const float* __restrict__ bs1,
                    const float* __restrict__ Wmu,
                    const float* __restrict__ bmu,
                    const float* __restrict__ Wvar,
                    const float* __restrict__ bvar,
                    const int*   __restrict__ sem_ids,
                    const int*   __restrict__ n_children,
                    float*       __restrict__ out)
{
    extern __shared__ float smem_raw[];
    Smem* S = (Smem*)smem_raw;
    const int t  = threadIdx.x;
    const int b0 = blockIdx.x * PT;
    const int rg = t >> 5;     // warp id, rows rg*8 .. rg*8+7
    const int cg = t & 31;
    const int c0 = 2 * cg;     // col pairs c0 + jp*64 + {0,1}

    // ---- stage per-tile inputs ----
    for (int i = t; i < PT * 100; i += NT) S->box[i] = box_input[b0 * 100 + i];
    for (int i = t; i < 10 * 256; i += NT) S->wbox[i] = W_box[i];
    if (t < 256) S->bbox[t] = b_box[t];
    for (int i = t; i < PT * 10; i += NT) S->sem[i] = sem_ids[b0 * 10 + i];
    if (t < PT) S->nc[t] = n_children[b0 + t];
    __syncthreads();

    float2 bb1[4];
    #pragma unroll
    for (int jp = 0; jp < 4; jp++) bb1[jp] = *(const float2*)&b1[c0 + jp * 64];

    float2 macc[8][4];
    #pragma unroll
    for (int i = 0; i < 8; i++)
        #pragma unroll
        for (int jp = 0; jp < 4; jp++) macc[i][jp] = make_float2(0.0f, 0.0f);

    // ---- children loop: leaf -> W1 GEMM -> masked max ----
    for (int m = 0; m < MAXC; m++) {
        __syncthreads();   // prior GEMM done reading As
        // leaf = relu(box @ W_box + b_box) for child m, into As [64][256]
        #pragma unroll 4
        for (int u = 0; u < (PT * 256) / NT; u++) {
            int i = t + u * NT;
            int r = i >> 8, f = i & 255;
            float s = S->bbox[f];
            const float* bx = &S->box[r * 100 + m * 10];
            #pragma unroll
            for (int q = 0; q < 10; q++) s += bx[q] * S->wbox[q * 256 + f];
            S->As[i] = fmaxf(s, 0.0f);
        }
        u64 facc[8][4];
        zero_acc(facc);
        gemm_64x256_p2(S->As, W1, S->Ws, t, rg, cg, facc);

        // epilogue: + one-hot row of W1 + b1, relu, masked running max
        #pragma unroll
        for (int i = 0; i < 8; i++) {
            int rr = rg * 8 + i;
            if (m < S->nc[rr]) {
                const float* wrow = W1 + ((256 + S->sem[rr * 10 + m]) << 8) + c0;
                #pragma unroll
                for (int jp = 0; jp < 4; jp++) {
                    float2 v = unpack2(facc[i][jp]);
                    float2 w = *(const float2*)&wrow[jp * 64];
                    float vx = fmaxf(v.x + w.x + bb1[jp].x, 0.0f);
                    float vy = fmaxf(v.y + w.y + bb1[jp].y, 0.0f);
                    macc[i][jp].x = fmaxf(macc[i][jp].x, vx);
                    macc[i][jp].y = fmaxf(macc[i][jp].y, vy);
                }
            }
        }
    }

    // ---- x = macc -> As ----
    __syncthreads();
    #pragma unroll
    for (int i = 0; i < 8; i++)
        #pragma unroll
        for (int jp = 0; jp < 4; jp++)
            *(float2*)&S->As[(rg * 8 + i) * 256 + c0 + jp * 64] = macc[i][jp];

    u64 acc[8][4];

    // ---- parent_feat = relu(X @ W2 + b2) -> As (in place after sync) ----
    zero_acc(acc);
    gemm_64x256_p2(S->As, W2, S->Ws, t, rg, cg, acc);
    __syncthreads();   // all readers of As done
    {
        #pragma unroll
        for (int jp = 0; jp < 4; jp++) {
            float2 bb = *(const float2*)&b2[c0 + jp * 64];
            #pragma unroll
            for (int i = 0; i < 8; i++) {
                float2 v = unpack2(acc[i][jp]);
                v.x = fmaxf(v.x + bb.x, 0.0f);
                v.y = fmaxf(v.y + bb.y, 0.0f);
                *(float2*)&S->As[(rg * 8 + i) * 256 + c0 + jp * 64] = v;
            }
        }
    }

    // ---- enc = relu(P @ Ws1 + bs1) -> As (in place) ----
    zero_acc(acc);
    gemm_64x256_p2(S->As, Ws1, S->Ws, t, rg, cg, acc);
    __syncthreads();
    {
        #pragma unroll
        for (int jp = 0; jp < 4; jp++) {
            float2 bb = *(const float2*)&bs1[c0 + jp * 64];
            #pragma unroll
            for (int i = 0; i < 8; i++) {
                float2 v = unpack2(acc[i][jp]);
                v.x = fmaxf(v.x + bb.x, 0.0f);
                v.y = fmaxf(v.y + bb.y, 0.0f);
                *(float2*)&S->As[(rg * 8 + i) * 256 + c0 + jp * 64] = v;
            }
        }
    }

    // ---- mu = enc @ Wmu + bmu (kept in regs) ----
    u64 muacc[8][4];
    zero_acc(muacc);
    gemm_64x256_p2(S->As, Wmu, S->Ws, t, rg, cg, muacc);

    // ---- logvar = enc @ Wvar + bvar, then sampler epilogue ----
    zero_acc(acc);
    gemm_64x256_p2(S->As, Wvar, S->Ws, t, rg, cg, acc);
    {
        #pragma unroll
        for (int jp = 0; jp < 4; jp++) {
            float2 bbv = *(const float2*)&bvar[c0 + jp * 64];
            float2 bbm = *(const float2*)&bmu[c0 + jp * 64];
            #pragma unroll
            for (int i = 0; i < 8; i++) {
                int b = b0 + rg * 8 + i;
                int c = c0 + jp * 64;
                float2 lv = unpack2(acc[i][jp]);
                float2 mv = unpack2(muacc[i][jp]);
                lv.x += bbv.x;  lv.y += bbv.y;
                mv.x += bbm.x;  mv.y += bbm.y;
                float2 e = *(const float2*)&eps[b * 256 + c];
                float sdx = expf(0.5f * lv.x);
                float sdy = expf(0.5f * lv.y);
                float2 samp, kld;
                samp.x = e.x * sdx + mv.x;
                samp.y = e.y * sdy + mv.y;
                kld.x = 1.0f + lv.x - mv.x * mv.x - sdx * sdx;
                kld.y = 1.0f + lv.y - mv.y * mv.y - sdy * sdy;
                *(float2*)&out[b * 512 + c]       = samp;
                *(float2*)&out[b * 512 + 256 + c] = kld;
            }
        }
    }
}

extern "C" void kernel_launch(void* const* d_in, const int* in_sizes, int n_in,
                              void* d_out, int out_size)
{
    const float* box   = (const float*)d_in[0];
    const float* eps   = (const float*)d_in[1];
    const float* W_box = (const float*)d_in[2];
    const float* b_box = (const float*)d_in[3];
    const float* W1    = (const float*)d_in[4];
    const float* b1    = (const float*)d_in[5];
    const float* W2    = (const float*)d_in[6];
    const float* b2    = (const float*)d_in[7];
    const float* Ws1   = (const float*)d_in[8];
    const float* bs1   = (const float*)d_in[9];
    const float* Wmu   = (const float*)d_in[10];
    const float* bmu   = (const float*)d_in[11];
    const float* Wvar  = (const float*)d_in[12];
    const float* bvar  = (const float*)d_in[13];
    const int*   sem   = (const int*)d_in[14];
    const int*   nc    = (const int*)d_in[15];
    float* out = (float*)d_out;

    size_t shmem = sizeof(Smem);
    cudaFuncSetAttribute(recenc_fused_kernel,
                         cudaFuncAttributeMaxDynamicSharedMemorySize, (int)shmem);
    recenc_fused_kernel<<<B_N / PT, NT, shmem>>>(
        box, eps, W_box, b_box, W1, b1, W2, b2,
        Ws1, bs1, Wmu, bmu, Wvar, bvar, sem, nc, out);
}

// round 6
// speedup vs baseline: 1.5416x; 1.2218x over previous
#include <cuda_runtime.h>
#include <cuda_bf16.h>
#include <cstdint>

// RecursiveEncoder — mma.sync (HMMA) bf16 3-term-split fused kernel.
// A (activations) hi/lo bf16 in smem, W (weights) pre-transposed+split in
// __device__ globals, staged per 32-k chunk into smem with register prefetch.
//
// Per block: 64 parents (M=64), 8 warps. Warp tile: M=32 (2 m-tiles), N=64
// (8 n-tiles), K=256. 3 MMAs per (kt,nt,mt): ah*bh + al*bh + ah*bl.

#define NT    256
#define PT    64
#define GRID  512           // 32768 / 64
#define MAXC  10

#define ASTR  264           // A row stride (bf16), 4r+c banks conflict-free
#define MSTR  260           // macc row stride (f32)
#define WSTR  40            // W chunk row stride (bf16): 20-word stride, conflict-free

// ---- smem offsets (bytes), all 16B aligned ----
#define OFF_AHI   0                       // 64 x 264 bf16 = 33792
#define OFF_ALO   33792                   // 33792
#define OFF_MACC  67584                   // 64 x 260 f32 = 66560
#define OFF_WCH   134144                  // 256 x 40 bf16 = 20480
#define OFF_WCL   154624                  // 20480
#define OFF_BOX   175104                  // 64 x 10 f32 = 2560
#define OFF_WBOX  177664                  // 10 x 256 f32 = 10240
#define OFF_BBOX  187904                  // 256 f32
#define OFF_B1    188928
#define OFF_B2    189952
#define OFF_BS1   190976
#define OFF_BMU   192000
#define OFF_BVAR  193024
#define OFF_SEM   194048                  // 64 x 10 int = 2560
#define OFF_NC    196608                  // 64 int
#define SMEM_SZ   196864

__device__ __nv_bfloat16 g_WT_hi[5 * 65536];   // [layer][n][k]
__device__ __nv_bfloat16 g_WT_lo[5 * 65536];

// ---- m16n8k16 bf16 MMA, f32 accum ----
static __device__ __forceinline__ void mma16816(float d[4], const uint32_t a[4],
                                                uint32_t b0, uint32_t b1)
{
    asm volatile(
        "mma.sync.aligned.m16n8k16.row.col.f32.bf16.bf16.f32 "
        "{%0,%1,%2,%3}, {%4,%5,%6,%7}, {%8,%9}, {%0,%1,%2,%3};"
        : "+f"(d[0]), "+f"(d[1]), "+f"(d[2]), "+f"(d[3])
        : "r"(a[0]), "r"(a[1]), "r"(a[2]), "r"(a[3]), "r"(b0), "r"(b1));
}

// ---- prep: transpose + bf16 hi/lo split of the 5 [256,256] weight mats ----
__global__ void prep_weights(const float* __restrict__ W1, const float* __restrict__ W2,
                             const float* __restrict__ Ws1, const float* __restrict__ Wmu,
                             const float* __restrict__ Wvar)
{
    int idx = blockIdx.x * blockDim.x + threadIdx.x;   // 5*65536
    int l = idx >> 16;
    int e = idx & 65535;
    int n = e >> 8, k = e & 255;
    const float* src = (l == 0) ? W1 : (l == 1) ? W2 : (l == 2) ? Ws1 : (l == 3) ? Wmu : Wvar;
    float v = src[k * 256 + n];
    __nv_bfloat16 h = __float2bfloat16(v);
    g_WT_hi[idx] = h;
    g_WT_lo[idx] = __float2bfloat16(v - __bfloat162float(h));
}

// ---- full K=256 GEMM: C[64x256] = A(hi+lo) @ W(hi+lo)^T, 3-term split ----
// Warp (wm, wn): rows wm*32..+31, cols wn*64..+63.
static __device__ __forceinline__ void gemm_tc(char* sm, int t, int wm, int wn, int lane,
                                               const __nv_bfloat16* __restrict__ whi,
                                               const __nv_bfloat16* __restrict__ wlo,
                                               float C[2][8][4])
{
    __nv_bfloat16* Ahi = (__nv_bfloat16*)(sm + OFF_AHI);
    __nv_bfloat16* Alo = (__nv_bfloat16*)(sm + OFF_ALO);
    __nv_bfloat16* Wh  = (__nv_bfloat16*)(sm + OFF_WCH);
    __nv_bfloat16* Wl  = (__nv_bfloat16*)(sm + OFF_WCL);

    #pragma unroll
    for (int mt = 0; mt < 2; mt++)
        #pragma unroll
        for (int nt = 0; nt < 8; nt++)
            #pragma unroll
            for (int q = 0; q < 4; q++) C[mt][nt][q] = 0.0f;

    // prefetch chunk 0 (thread t owns weight row n = t, 32 k at a time)
    uint4 ph[4], pl[4];
    {
        const uint4* gh = (const uint4*)(whi + t * 256);
        const uint4* gl = (const uint4*)(wlo + t * 256);
        #pragma unroll
        for (int q = 0; q < 4; q++) { ph[q] = gh[q]; pl[q] = gl[q]; }
    }

    #pragma unroll 1
    for (int c = 0; c < 8; c++) {
        __syncthreads();   // consumers of previous chunk done
        {
            uint4* dh = (uint4*)(Wh + t * WSTR);
            uint4* dl = (uint4*)(Wl + t * WSTR);
            #pragma unroll
            for (int q = 0; q < 4; q++) { dh[q] = ph[q]; dl[q] = pl[q]; }
        }
        __syncthreads();
        if (c < 7) {
            const uint4* gh = (const uint4*)(whi + t * 256 + (c + 1) * 32);
            const uint4* gl = (const uint4*)(wlo + t * 256 + (c + 1) * 32);
            #pragma unroll
            for (int q = 0; q < 4; q++) { ph[q] = gh[q]; pl[q] = gl[q]; }
        }
        #pragma unroll
        for (int ktl = 0; ktl < 2; ktl++) {
            const int kabs = c * 32 + ktl * 16 + (lane & 3) * 2;
            uint32_t ah[2][4], al[2][4];
            #pragma unroll
            for (int mt = 0; mt < 2; mt++) {
                int r0 = wm * 32 + mt * 16 + (lane >> 2);
                const __nv_bfloat16* p = Ahi + r0 * ASTR + kabs;
                ah[mt][0] = *(const uint32_t*)(p);
                ah[mt][1] = *(const uint32_t*)(p + 8 * ASTR);
                ah[mt][2] = *(const uint32_t*)(p + 8);
                ah[mt][3] = *(const uint32_t*)(p + 8 * ASTR + 8);
                const __nv_bfloat16* q = Alo + r0 * ASTR + kabs;
                al[mt][0] = *(const uint32_t*)(q);
                al[mt][1] = *(const uint32_t*)(q + 8 * ASTR);
                al[mt][2] = *(const uint32_t*)(q + 8);
                al[mt][3] = *(const uint32_t*)(q + 8 * ASTR + 8);
            }
            const int klocal = ktl * 16 + (lane & 3) * 2;
            const int nbase = wn * 64 + (lane >> 2);
            #pragma unroll
            for (int nt = 0; nt < 8; nt++) {
                const __nv_bfloat16* bp = Wh + (nbase + nt * 8) * WSTR + klocal;
                uint32_t b0h = *(const uint32_t*)(bp);
                uint32_t b1h = *(const uint32_t*)(bp + 8);
                const __nv_bfloat16* bq = Wl + (nbase + nt * 8) * WSTR + klocal;
                uint32_t b0l = *(const uint32_t*)(bq);
                uint32_t b1l = *(const uint32_t*)(bq + 8);
                mma16816(C[0][nt], ah[0], b0h, b1h);
                mma16816(C[1][nt], ah[1], b0h, b1h);
                mma16816(C[0][nt], al[0], b0h, b1h);
                mma16816(C[1][nt], al[1], b0h, b1h);
                mma16816(C[0][nt], ah[0], b0l, b1l);
                mma16816(C[1][nt], ah[1], b0l, b1l);
            }
        }
    }
    __syncthreads();   // all warps done reading A/W before caller mutates them
}

// split f32 value into bf16 hi/lo buffers
static __device__ __forceinline__ void split_store(__nv_bfloat16* Ahi, __nv_bfloat16* Alo,
                                                   int idx, float v)
{
    __nv_bfloat16 h = __float2bfloat16(v);
    Ahi[idx] = h;
    Alo[idx] = __float2bfloat16(v - __bfloat162float(h));
}

__global__ void __launch_bounds__(NT, 1)
recenc_tc_kernel(const float* __restrict__ box_input,
                 const float* __restrict__ eps,
                 const float* __restrict__ W_box,
                 const float* __restrict__ b_box,
                 const float* __restrict__ W1,
                 const float* __restrict__ b1,
                 const float* __restrict__ b2,
                 const float* __restrict__ bs1,
                 const float* __restrict__ bmu,
                 const float* __restrict__ bvar,
                 const int*   __restrict__ sem_ids,
                 const int*   __restrict__ n_children,
                 float*       __restrict__ out)
{
    extern __shared__ char sm[];
    __nv_bfloat16* Ahi = (__nv_bfloat16*)(sm + OFF_AHI);
    __nv_bfloat16* Alo = (__nv_bfloat16*)(sm + OFF_ALO);
    float* maccS = (float*)(sm + OFF_MACC);
    float* boxS  = (float*)(sm + OFF_BOX);
    float* wboxS = (float*)(sm + OFF_WBOX);
    float* bboxS = (float*)(sm + OFF_BBOX);
    float* b1S   = (float*)(sm + OFF_B1);
    float* b2S   = (float*)(sm + OFF_B2);
    float* bs1S  = (float*)(sm + OFF_BS1);
    float* bmuS  = (float*)(sm + OFF_BMU);
    float* bvarS = (float*)(sm + OFF_BVAR);
    int*   semS  = (int*)(sm + OFF_SEM);
    int*   ncS   = (int*)(sm + OFF_NC);

    const int t = threadIdx.x;
    const int wid = t >> 5;
    const int lane = t & 31;
    const int wm = wid >> 2;      // 0..1
    const int wn = wid & 3;       // 0..3
    const int b0 = blockIdx.x * PT;

    // ---- stage constants + zero macc ----
    for (int i = t; i < 10 * 256; i += NT) wboxS[i] = W_box[i];
    if (t < 256) {
        bboxS[t] = b_box[t];
        b1S[t]   = b1[t];
        b2S[t]   = b2[t];
        bs1S[t]  = bs1[t];
        bmuS[t]  = bmu[t];
        bvarS[t] = bvar[t];
    }
    for (int i = t; i < PT * 10; i += NT) semS[i] = sem_ids[b0 * 10 + i];
    if (t < PT) ncS[t] = n_children[b0 + t];
    for (int i = t; i < PT * MSTR; i += NT) maccS[i] = 0.0f;

    float C[2][8][4];

    // ---- children: leaf -> GEMM(W1) -> masked max into maccS ----
    for (int m = 0; m < MAXC; m++) {
        // stage this child's box rows (previous GEMM's trailing sync protects)
        for (int i = t; i < PT * 10; i += NT)
            boxS[i] = box_input[(b0 + i / 10) * 100 + m * 10 + (i % 10)];
        __syncthreads();

        // leaf = relu(box @ Wbox + bbox) -> A hi/lo
        #pragma unroll 1
        for (int u = 0; u < (PT * 256) / NT; u++) {
            int i = t + u * NT;
            int r = i >> 8, f = i & 255;
            float s = bboxS[f];
            const float* bx = &boxS[r * 10];
            #pragma unroll
            for (int q = 0; q < 10; q++) s += bx[q] * wboxS[q * 256 + f];
            split_store(Ahi, Alo, r * ASTR + f, fmaxf(s, 0.0f));
        }

        gemm_tc(sm, t, wm, wn, lane, g_WT_hi, g_WT_lo, C);

        // epilogue: feat = relu(C + W1[256+sem] + b1); macc = max(macc, feat)
        #pragma unroll
        for (int mt = 0; mt < 2; mt++) {
            #pragma unroll
            for (int half = 0; half < 2; half++) {
                int r = wm * 32 + mt * 16 + (lane >> 2) + half * 8;
                if (m < ncS[r]) {
                    const float* wrow = W1 + ((256 + semS[r * 10 + m]) << 8);
                    #pragma unroll
                    for (int nt = 0; nt < 8; nt++) {
                        int col = wn * 64 + nt * 8 + (lane & 3) * 2;
                        float2 w  = *(const float2*)&wrow[col];
                        float2 bb = *(const float2*)&b1S[col];
                        float v0 = fmaxf(C[mt][nt][half * 2 + 0] + w.x + bb.x, 0.0f);
                        float v1 = fmaxf(C[mt][nt][half * 2 + 1] + w.y + bb.y, 0.0f);
                        float2* mp = (float2*)&maccS[r * MSTR + col];
                        float2 mo = *mp;
                        mo.x = fmaxf(mo.x, v0);
                        mo.y = fmaxf(mo.y, v1);
                        *mp = mo;
                    }
                }
            }
        }
        __syncthreads();   // macc/epilogue done before next child's leaf write
    }

    // ---- helper lambda-ish: split macc -> A ----
    // (A readers all passed gemm's trailing sync; macc writers synced above)
    #define SPLIT_MACC_TO_A()                                              \
        do {                                                               \
            for (int u = 0; u < (PT * 256) / NT; u++) {                    \
                int i = t + u * NT;                                        \
                int r = i >> 8, f = i & 255;                               \
                split_store(Ahi, Alo, r * ASTR + f, maccS[r * MSTR + f]);  \
            }                                                              \
        } while (0)

    // ---- parent_feat = relu(X @ W2 + b2) ----
    SPLIT_MACC_TO_A();
    gemm_tc(sm, t, wm, wn, lane, g_WT_hi + 1 * 65536, g_WT_lo + 1 * 65536, C);
    #pragma unroll
    for (int mt = 0; mt < 2; mt++)
        #pragma unroll
        for (int half = 0; half < 2; half++) {
            int r = wm * 32 + mt * 16 + (lane >> 2) + half * 8;
            #pragma unroll
            for (int nt = 0; nt < 8; nt++) {
                int col = wn * 64 + nt * 8 + (lane & 3) * 2;
                float2 bb = *(const float2*)&b2S[col];
                float2 v;
                v.x = fmaxf(C[mt][nt][half * 2 + 0] + bb.x, 0.0f);
                v.y = fmaxf(C[mt][nt][half * 2 + 1] + bb.y, 0.0f);
                *(float2*)&maccS[r * MSTR + col] = v;
            }
        }
    __syncthreads();

    // ---- enc = relu(P @ Ws1 + bs1) ----
    SPLIT_MACC_TO_A();
    gemm_tc(sm, t, wm, wn, lane, g_WT_hi + 2 * 65536, g_WT_lo + 2 * 65536, C);
    #pragma unroll
    for (int mt = 0; mt < 2; mt++)
        #pragma unroll
        for (int half = 0; half < 2; half++) {
            int r = wm * 32 + mt * 16 + (lane >> 2) + half * 8;
            #pragma unroll
            for (int nt = 0; nt < 8; nt++) {
                int col = wn * 64 + nt * 8 + (lane & 3) * 2;
                float2 bb = *(const float2*)&bs1S[col];
                float2 v;
                v.x = fmaxf(C[mt][nt][half * 2 + 0] + bb.x, 0.0f);
                v.y = fmaxf(C[mt][nt][half * 2 + 1] + bb.y, 0.0f);
                *(float2*)&maccS[r * MSTR + col] = v;
            }
        }
    __syncthreads();

    // ---- mu = enc @ Wmu + bmu -> macc (A holds enc; kept for Wvar) ----
    SPLIT_MACC_TO_A();   // NOTE: reads enc from macc, writes A; macc then reused for mu
    gemm_tc(sm, t, wm, wn, lane, g_WT_hi + 3 * 65536, g_WT_lo + 3 * 65536, C);
    #pragma unroll
    for (int mt = 0; mt < 2; mt++)
        #pragma unroll
        for (int half = 0; half < 2; half++) {
            int r = wm * 32 + mt * 16 + (lane >> 2) + half * 8;
            #pragma unroll
            for (int nt = 0; nt < 8; nt++) {
                int col = wn * 64 + nt * 8 + (lane & 3) * 2;
                float2 bb = *(const float2*)&bmuS[col];
                float2 v;
                v.x = C[mt][nt][half * 2 + 0] + bb.x;
                v.y = C[mt][nt][half * 2 + 1] + bb.y;
                *(float2*)&maccS[r * MSTR + col] = v;
            }
        }
    // no A mutation between here and Wvar GEMM; gemm's first sync orders macc writes

    // ---- logvar = enc @ Wvar + bvar; sampler epilogue ----
    gemm_tc(sm, t, wm, wn, lane, g_WT_hi + 4 * 65536, g_WT_lo + 4 * 65536, C);
    // A no longer needed: reuse AHI+ALO region as f32 kld buffer [64][264]
    float* kldS = (float*)(sm + OFF_AHI);
    #pragma unroll
    for (int mt = 0; mt < 2; mt++)
        #pragma unroll
        for (int half = 0; half < 2; half++) {
            int r = wm * 32 + mt * 16 + (lane >> 2) + half * 8;
            int b = b0 + r;
            #pragma unroll
            for (int nt = 0; nt < 8; nt++) {
                int col = wn * 64 + nt * 8 + (lane & 3) * 2;
                float2 bb = *(const float2*)&bvarS[col];
                float2 mv = *(const float2*)&maccS[r * MSTR + col];
                float2 e  = *(const float2*)&eps[b * 256 + col];
                float lvx = C[mt][nt][half * 2 + 0] + bb.x;
                float lvy = C[mt][nt][half * 2 + 1] + bb.y;
                float sdx = expf(0.5f * lvx);
                float sdy = expf(0.5f * lvy);
                float2 samp, kld;
                samp.x = e.x * sdx + mv.x;
                samp.y = e.y * sdy + mv.y;
                kld.x = 1.0f + lvx - mv.x * mv.x - sdx * sdx;
                kld.y = 1.0f + lvy - mv.y * mv.y - sdy * sdy;
                *(float2*)&maccS[r * MSTR + col] = samp;   // overwrite mu (same lane owns it)
                *(float2*)&kldS[r * ASTR + col] = kld;
            }
        }
    __syncthreads();

    // ---- coalesced output sweep ----
    #pragma unroll 1
    for (int u = 0; u < (PT * 256) / NT; u++) {
        int i = t + u * NT;
        int r = i >> 8, f = i & 255;
        out[(b0 + r) * 512 + f]       = maccS[r * MSTR + f];
        out[(b0 + r) * 512 + 256 + f] = kldS[r * ASTR + f];
    }
}

// ================= launch =================
extern "C" void kernel_launch(void* const* d_in, const int* in_sizes, int n_in,
                              void* d_out, int out_size)
{
    const float* box   = (const float*)d_in[0];
    const float* eps   = (const float*)d_in[1];
    const float* W_box = (const float*)d_in[2];
    const float* b_box = (const float*)d_in[3];
    const float* W1    = (const float*)d_in[4];
    const float* b1    = (const float*)d_in[5];
    const float* W2    = (const float*)d_in[6];
    const float* b2    = (const float*)d_in[7];
    const float* Ws1   = (const float*)d_in[8];
    const float* bs1   = (const float*)d_in[9];
    const float* Wmu   = (const float*)d_in[10];
    const float* bmu   = (const float*)d_in[11];
    const float* Wvar  = (const float*)d_in[12];
    const float* bvar  = (const float*)d_in[13];
    const int*   sem   = (const int*)d_in[14];
    const int*   nc    = (const int*)d_in[15];
    float* out = (float*)d_out;

    prep_weights<<<(5 * 65536) / 256, 256>>>(W1, W2, Ws1, Wmu, Wvar);

    cudaFuncSetAttribute(recenc_tc_kernel,
                         cudaFuncAttributeMaxDynamicSharedMemorySize, SMEM_SZ);
    recenc_tc_kernel<<<GRID, NT, SMEM_SZ>>>(
        box, eps, W_box, b_box, W1, b1, b2, bs1, bmu, bvar, sem, nc, out);
}